// round 13
// baseline (speedup 1.0000x reference)
#include <cuda_runtime.h>
#include <cstdint>

#define H 512
#define TOT (16*256*256)
#define HALF (TOT/2)
#define SCALE_INV 0.1f
#define STRENGTH 5.0f

typedef unsigned long long u64;

// ---------- packed f32x2 helpers ----------
__device__ __forceinline__ u64 pk(float lo, float hi) {
    u64 r; asm("mov.b64 %0, {%1, %2};" : "=l"(r) : "f"(lo), "f"(hi)); return r;
}
__device__ __forceinline__ void upk(u64 v, float& lo, float& hi) {
    asm("mov.b64 {%0, %1}, %2;" : "=f"(lo), "=f"(hi) : "l"(v));
}
__device__ __forceinline__ u64 fma2(u64 a, u64 b, u64 c) {
    u64 d; asm("fma.rn.f32x2 %0, %1, %2, %3;" : "=l"(d) : "l"(a), "l"(b), "l"(c)); return d;
}
__device__ __forceinline__ u64 cos2(u64 v) {
    float lo, hi; upk(v, lo, hi);
    return pk(__cosf(lo), __cosf(hi));
}

// ---------- weights on the constant-cache port ----------
// c_w1: all of layer 1.  c_w2h: layer-2 rows k in [0,16).
// The remaining layer-2 rows stay in shared -> the const port and the L1
// crossbar each carry about half the weight traffic, both under the fma roof.
__constant__ ulonglong2 c_w1[256];    // [k*8+q]  = w1 row k,  cols 4q..4q+3
__constant__ ulonglong2 c_w2h[128];   // [k*8+q]  = w2 row k (k<16), cols 4q..4q+3

// ---------- prelude results ----------
__device__ float g_A[4];
__device__ __align__(8) float g_bns[32];
__device__ __align__(8) float g_bno[32];

__global__ void prelude_kernel(const float* __restrict__ gen,
                               const float* __restrict__ gam,
                               const float* __restrict__ bet,
                               const float* __restrict__ mean,
                               const float* __restrict__ var) {
    int t = threadIdx.x;
    if (t == 0) {
        double m0 = gen[0], m1 = gen[1], m2 = gen[2], m3 = gen[3];
        double a0 = 1.0, a1 = 0.0, a2 = 0.0, a3 = 1.0;
        double t0 = 1.0, t1 = 0.0, t2 = 0.0, t3 = 1.0;
        for (int k = 1; k <= 18; k++) {
            double n0 = (t0 * m0 + t1 * m2) / k;
            double n1 = (t0 * m1 + t1 * m3) / k;
            double n2 = (t2 * m0 + t3 * m2) / k;
            double n3 = (t2 * m1 + t3 * m3) / k;
            t0 = n0; t1 = n1; t2 = n2; t3 = n3;
            a0 += n0; a1 += n1; a2 += n2; a3 += n3;
        }
        g_A[0] = (float)a0; g_A[1] = (float)a1;
        g_A[2] = (float)a2; g_A[3] = (float)a3;
    }
    if (t < 32) {
        float s = gam[t] * rsqrtf(var[t] + 0.001f);
        g_bns[t] = s;
        g_bno[t] = bet[t] - mean[t] * s;
    }
}

// ---------- bilinear sample ----------
__device__ __forceinline__ float bil(const float* __restrict__ img, float r, float c) {
    r = fminf(fmaxf(r, 0.0f), (float)(H - 1));
    c = fminf(fmaxf(c, 0.0f), (float)(H - 1));
    float rf = floorf(r), cf = floorf(c);
    int r0 = (int)rf, c0 = (int)cf;
    int r1 = min(r0 + 1, H - 1), c1 = min(c0 + 1, H - 1);
    float wr = r - rf, wc = c - cf;
    float v00 = __ldg(img + r0 * H + c0);
    float v01 = __ldg(img + r0 * H + c1);
    float v10 = __ldg(img + r1 * H + c0);
    float v11 = __ldg(img + r1 * H + c1);
    float top = v00 + wc * (v01 - v00);
    float bot = v10 + wc * (v11 - v10);
    return top + wr * (bot - top);
}

// ---------- main kernel ----------
// 2 px/thread, f32x2 lanes = two adjacent OUTPUT columns.
//  - layer0 fused into layer1 k-loop
//  - layer1 weights: __constant__
//  - layer2 weights: k<16 __constant__, k>=16 shared  <- only change vs R12
#define BLK 128
__global__ __launch_bounds__(BLK, 4)
void rmodel_kernel(const float* __restrict__ x,
                   const float* __restrict__ trans,
                   const float* __restrict__ w0, const float* __restrict__ b0,
                   const float* __restrict__ b1,
                   const float* __restrict__ w2, const float* __restrict__ b2,
                   const float* __restrict__ wf,
                   const float* __restrict__ img,
                   float* __restrict__ out) {
    __shared__ ulonglong2 s_w2[128];   // [(k-16)*8+q] = w2 row k (k>=16)
    __shared__ ulonglong2 s_l0[32];    // [k]: .x = dup w0[0][k], .y = dup w0[1][k]
    __shared__ u64 s_l0b[32];          // dup b0[k]
    __shared__ u64 s_b1[16], s_b2[16];
    __shared__ u64 s_bns[16], s_bno[16];
    __shared__ ulonglong2 s_wf[16];    // [j] = {wf rows 2j, 2j+1}

    int tid = threadIdx.x;
    {
        const ulonglong2* gw2 = (const ulonglong2*)w2;
        if (tid < 128) s_w2[tid] = gw2[128 + tid];   // rows 16..31
        if (tid < 32) {
            float wa = w0[tid], wb = w0[32 + tid], bb = b0[tid];
            s_l0[tid] = make_ulonglong2(pk(wa, wa), pk(wb, wb));
            s_l0b[tid] = pk(bb, bb);
        }
        if (tid < 16) {
            s_wf[tid]  = ((const ulonglong2*)wf)[tid];
            s_b1[tid]  = ((const u64*)b1)[tid];
            s_b2[tid]  = ((const u64*)b2)[tid];
            s_bns[tid] = pk(g_bns[2 * tid], g_bns[2 * tid + 1]);
            s_bno[tid] = pk(g_bno[2 * tid], g_bno[2 * tid + 1]);
        }
    }
    __syncthreads();

    int i = blockIdx.x * BLK + tid;           // pixels (i, i+HALF)
    int ib = i + HALF;

    float xa0 = __ldg(x + 3 * i),  xa1 = __ldg(x + 3 * i + 1);
    float xb0 = __ldg(x + 3 * ib), xb1 = __ldg(x + 3 * ib + 1);

    float A0 = g_A[0], A1 = g_A[1], A2 = g_A[2], A3 = g_A[3];
    float t0 = __ldg(trans), t1 = __ldg(trans + 1);

    float ca0 = fmaf(A0, xa0, fmaf(A1, xa1, t0));
    float ca1 = fmaf(A2, xa0, fmaf(A3, xa1, t1));
    float cb0 = fmaf(A0, xb0, fmaf(A1, xb1, t0));
    float cb1 = fmaf(A2, xb0, fmaf(A3, xb1, t1));

    // lanes of pa* = pixels {A, B}
    u64 pa0 = pk(ca0 * SCALE_INV, cb0 * SCALE_INV);
    u64 pa1 = pk(ca1 * SCALE_INV, cb1 * SCALE_INV);

    // ---- layer 1 (layer 0 fused into k-loop), weights from constant ----
    u64 accA[16], accB[16];
    #pragma unroll
    for (int jp = 0; jp < 16; jp++) { u64 b = s_b1[jp]; accA[jp] = b; accB[jp] = b; }

    #pragma unroll 4
    for (int k = 0; k < 32; k++) {
        ulonglong2 w0k = s_l0[k];
        u64 arg = fma2(pa0, w0k.x, fma2(pa1, w0k.y, s_l0b[k]));
        float uA, uB; upk(arg, uA, uB);
        float ykA = __cosf(uA), ykB = __cosf(uB);
        u64 da = pk(ykA, ykA), db = pk(ykB, ykB);
        #pragma unroll
        for (int q = 0; q < 8; q++) {
            ulonglong2 w = c_w1[k * 8 + q];
            accA[2 * q]     = fma2(da, w.x, accA[2 * q]);
            accA[2 * q + 1] = fma2(da, w.y, accA[2 * q + 1]);
            accB[2 * q]     = fma2(db, w.x, accB[2 * q]);
            accB[2 * q + 1] = fma2(db, w.y, accB[2 * q + 1]);
        }
    }

    // z = cos(acc), stored as f32 (acc regs freed after this)
    float zA[32], zB[32];
    #pragma unroll
    for (int jp = 0; jp < 16; jp++) {
        float u, v;
        upk(accA[jp], u, v); zA[2 * jp] = __cosf(u); zA[2 * jp + 1] = __cosf(v);
        upk(accB[jp], u, v); zB[2 * jp] = __cosf(u); zB[2 * jp + 1] = __cosf(v);
    }

    // ---- layer 2 in two column-halves + fused BN/cos + partial wf proj ----
    // k<16 weights from constant, k>=16 from shared.
    u64 dA = 0ull, dB = 0ull;
    #pragma unroll
    for (int h = 0; h < 2; h++) {
        u64 a2A[8], a2B[8];
        #pragma unroll
        for (int jp = 0; jp < 8; jp++) { u64 b = s_b2[8 * h + jp]; a2A[jp] = b; a2B[jp] = b; }
        #pragma unroll
        for (int k = 0; k < 32; k++) {
            u64 da = pk(zA[k], zA[k]);
            u64 db = pk(zB[k], zB[k]);
            #pragma unroll
            for (int q = 0; q < 4; q++) {
                ulonglong2 w = (k < 16) ? c_w2h[k * 8 + 4 * h + q]
                                        : s_w2[(k - 16) * 8 + 4 * h + q];
                a2A[2 * q]     = fma2(da, w.x, a2A[2 * q]);
                a2A[2 * q + 1] = fma2(da, w.y, a2A[2 * q + 1]);
                a2B[2 * q]     = fma2(db, w.x, a2B[2 * q]);
                a2B[2 * q + 1] = fma2(db, w.y, a2B[2 * q + 1]);
            }
        }
        #pragma unroll
        for (int jp = 0; jp < 8; jp++) {
            int j = 8 * h + jp;                 // global column-pair
            u64 s = s_bns[j], o = s_bno[j];
            ulonglong2 wfp = s_wf[j];           // wf rows 2j, 2j+1
            u64 qa = cos2(fma2(cos2(a2A[jp]), s, o));
            u64 qb = cos2(fma2(cos2(a2B[jp]), s, o));
            float f0, f1;
            upk(qa, f0, f1);
            dA = fma2(pk(f0, f0), wfp.x, dA);
            dA = fma2(pk(f1, f1), wfp.y, dA);
            upk(qb, f0, f1);
            dB = fma2(pk(f0, f0), wfp.x, dB);
            dB = fma2(pk(f1, f1), wfp.y, dB);
        }
    }

    u64 five = pk(STRENGTH, STRENGTH);
    u64 cfA = fma2(five, dA, pk(ca0, ca1));
    u64 cfB = fma2(five, dB, pk(cb0, cb1));

    float ra, rca, rb, rcb;
    upk(cfA, ra, rca);
    upk(cfB, rb, rcb);

    out[i]  = bil(img, ra, rca);
    out[ib] = bil(img, rb, rcb);
}

extern "C" void kernel_launch(void* const* d_in, const int* in_sizes, int n_in,
                              void* d_out, int out_size) {
    const float* x      = (const float*)d_in[0];
    const float* gen    = (const float*)d_in[1];
    const float* trans  = (const float*)d_in[2];
    const float* w0     = (const float*)d_in[3];
    const float* b0     = (const float*)d_in[4];
    const float* w1     = (const float*)d_in[5];
    const float* b1     = (const float*)d_in[6];
    const float* w2     = (const float*)d_in[7];
    const float* b2     = (const float*)d_in[8];
    const float* gam    = (const float*)d_in[9];
    const float* bet    = (const float*)d_in[10];
    const float* mean   = (const float*)d_in[11];
    const float* var    = (const float*)d_in[12];
    const float* wf     = (const float*)d_in[13];
    const float* img    = (const float*)d_in[14];
    float* out = (float*)d_out;

    // Stage weights into constant memory (async D2D, graph-capturable)
    cudaMemcpyToSymbolAsync(c_w1, w1, 1024 * sizeof(float), 0,
                            cudaMemcpyDeviceToDevice);
    cudaMemcpyToSymbolAsync(c_w2h, w2, 512 * sizeof(float), 0,
                            cudaMemcpyDeviceToDevice);

    prelude_kernel<<<1, 32>>>(gen, gam, bet, mean, var);
    rmodel_kernel<<<HALF / BLK, BLK>>>(x, trans, w0, b0, b1, w2, b2,
                                       wf, img, out);
}